// round 13
// baseline (speedup 1.0000x reference)
#include <cuda_runtime.h>
#include <cuda_bf16.h>
#include <cstdint>

// VectorQuantizer: N=262144 rows, D=64, K=1024 codes, fp32.
//
// Round 13: SINGLE sweep. Capture threshold solved without R10's per-tile
// poison: chunk 0 (16 tiles) does per-tile row-min shfl exchange (bounded,
// hidden at occ 2), seeding every lane with the true 128-code row min;
// chunks 1-7 capture against min(lane running min, chunk-boundary row min)
// with NO in-loop shfl. Slots 28, deterministic capture set, exact full-scan
// fallback on overflow. Everything else = R12 (occ 2, cp.async 2-stage
// codebook stream, prep kernel, fused ticket loss).
// Exact selection (validated, bit-identical): M = serial ascending-d fmaf
// chain, t = Sx + Se, d = fmaf(-2, M, t), argmin strict < ascending k.

#define VQ_N       262144
#define VQ_D       64
#define VQ_K       1024
#define VQ_TPB     256
#define VQ_ROWS_PB 256                    // 8 warps x 32 rows
#define VQ_GRID    (VQ_N / VQ_ROWS_PB)   // 1024 blocks
#define VQ_EPAD    72                    // padded bf16 row (144B)
#define VQ_CHUNK   128                   // codes per pipeline stage
#define VQ_NCHUNK  (VQ_K / VQ_CHUNK)     // 8
#define VQ_SLOTS   28
#define VQ_MARGIN  1e-3f

#define VQ_CHUNK_B (VQ_CHUNK * VQ_EPAD * 2)   // 18432 bytes per stage
#define VQ_SMEM_E  (2 * VQ_CHUNK_B)           // 36864 bytes dynamic

__device__ __nv_bfloat16 g_cbh[VQ_K * VQ_EPAD];
__device__ float         g_Se[VQ_K];
__device__ float         g_vq_partial[VQ_GRID];
__device__ unsigned int  g_vq_ticket;

__device__ __forceinline__ uint32_t pack_bf16x2(float lo, float hi) {
    __nv_bfloat162 h = __float22bfloat162_rn(make_float2(lo, hi));
    return *reinterpret_cast<uint32_t*>(&h);
}

__device__ __forceinline__ void mma_bf16(float& c0, float& c1, float& c2, float& c3,
                                         uint32_t a0, uint32_t a1, uint32_t a2, uint32_t a3,
                                         uint32_t b0, uint32_t b1) {
    asm volatile(
        "mma.sync.aligned.m16n8k16.row.col.f32.bf16.bf16.f32 "
        "{%0,%1,%2,%3},{%4,%5,%6,%7},{%8,%9},{%0,%1,%2,%3};"
        : "+f"(c0), "+f"(c1), "+f"(c2), "+f"(c3)
        : "r"(a0), "r"(a1), "r"(a2), "r"(a3), "r"(b0), "r"(b1));
}

__device__ __forceinline__ void ldsm_x4(uint32_t& r0, uint32_t& r1, uint32_t& r2, uint32_t& r3,
                                        uint32_t addr) {
    asm volatile("ldmatrix.sync.aligned.m8n8.x4.shared.b16 {%0,%1,%2,%3}, [%4];"
                 : "=r"(r0), "=r"(r1), "=r"(r2), "=r"(r3) : "r"(addr));
}

__device__ __forceinline__ void cp_async16(uint32_t dst_smem, const void* src) {
    asm volatile("cp.async.cg.shared.global [%0], [%1], 16;"
                 :: "r"(dst_smem), "l"(src));
}
__device__ __forceinline__ void cp_commit() { asm volatile("cp.async.commit_group;"); }
__device__ __forceinline__ void cp_wait1()  { asm volatile("cp.async.wait_group 1;"); }
__device__ __forceinline__ void cp_wait0()  { asm volatile("cp.async.wait_group 0;"); }

__device__ __forceinline__ float exact_dist_stream(const float4* __restrict__ xp, float Sx,
                                                   const float* __restrict__ cb,
                                                   const float* __restrict__ se, int idx) {
    const float4* e4 = reinterpret_cast<const float4*>(cb + (size_t)idx * VQ_D);
    float m = 0.0f;
    #pragma unroll
    for (int i = 0; i < VQ_D / 4; i++) {
        float4 q = e4[i], xv = xp[i];
        m = fmaf(xv.x, q.x, m); m = fmaf(xv.y, q.y, m);
        m = fmaf(xv.z, q.z, m); m = fmaf(xv.w, q.w, m);
    }
    float t = Sx + se[idx];
    return fmaf(-2.0f, m, t);
}

__global__ void vq_prep_kernel(const float* __restrict__ cb)
{
    int code = blockIdx.x * blockDim.x + threadIdx.x;
    if (code < VQ_K) {
        const float4* e4 = reinterpret_cast<const float4*>(cb + (size_t)code * VQ_D);
        uint32_t* dst = reinterpret_cast<uint32_t*>(g_cbh + code * VQ_EPAD);
        float s = 0.0f;
        #pragma unroll
        for (int i = 0; i < VQ_D / 4; i++) {
            float4 q = e4[i];
            s = fmaf(q.x, q.x, s); s = fmaf(q.y, q.y, s);
            s = fmaf(q.z, q.z, s); s = fmaf(q.w, q.w, s);
            dst[2 * i]     = pack_bf16x2(q.x, q.y);
            dst[2 * i + 1] = pack_bf16x2(q.z, q.w);
        }
        g_Se[code] = s;
    }
}

extern __shared__ __nv_bfloat16 s_stage[];   // 2 x VQ_CHUNK_B

__device__ __forceinline__ void copy_chunk(int ch, uint32_t s_base, int tid) {
    const char* src = reinterpret_cast<const char*>(g_cbh) + (size_t)ch * VQ_CHUNK_B;
    uint32_t dst = s_base + (uint32_t)((ch & 1) * VQ_CHUNK_B);
    #pragma unroll
    for (int i = tid; i < VQ_CHUNK_B / 16; i += VQ_TPB)
        cp_async16(dst + (uint32_t)(i * 16), src + i * 16);
    cp_commit();
}

__global__ void __launch_bounds__(VQ_TPB, 2)
vq_main_kernel(const float* __restrict__ x,
               const float* __restrict__ cb,
               float* __restrict__ out,
               int write_q, long long out_size)
{
    __shared__ float  s_Se[VQ_K];
    __shared__ float  s_rowmin[VQ_ROWS_PB];
    __shared__ int    s_cnt[VQ_ROWS_PB];
    __shared__ int    s_cand[VQ_ROWS_PB][VQ_SLOTS];
    __shared__ int    s_win[VQ_ROWS_PB];
    __shared__ float  s_red[VQ_TPB];
    __shared__ int    s_last;
    __shared__ double s_dred[VQ_TPB];

    const int tid  = threadIdx.x;
    const int wid  = tid >> 5;
    const int lane = tid & 31;
    const int g    = lane >> 2;
    const int tg   = lane & 3;
    const int rowbase = blockIdx.x * VQ_ROWS_PB;
    const int r0 = wid * 32 + g;
    const int r1 = r0 + 8;
    const int r2 = r0 + 16;
    const int r3 = r0 + 24;

    #pragma unroll
    for (int c = 0; c < VQ_K / VQ_TPB; c++)
        s_Se[tid + c * VQ_TPB] = g_Se[tid + c * VQ_TPB];
    s_cnt[tid] = 0;

    // ---- A fragments: warp's 32 rows as two m16 tiles, bf16 in regs ----
    uint32_t afr0[4][4], afr1[4][4];
    {
        const float* xa = x + (size_t)(rowbase + r0) * VQ_D;
        const float* xb = xa + 8 * VQ_D;
        const float* xc = xa + 16 * VQ_D;
        const float* xd = xa + 24 * VQ_D;
        #pragma unroll
        for (int kt = 0; kt < 4; kt++) {
            int c = kt * 16 + 2 * tg;
            afr0[kt][0] = pack_bf16x2(xa[c],     xa[c + 1]);
            afr0[kt][1] = pack_bf16x2(xb[c],     xb[c + 1]);
            afr0[kt][2] = pack_bf16x2(xa[c + 8], xa[c + 9]);
            afr0[kt][3] = pack_bf16x2(xb[c + 8], xb[c + 9]);
            afr1[kt][0] = pack_bf16x2(xc[c],     xc[c + 1]);
            afr1[kt][1] = pack_bf16x2(xd[c],     xd[c + 1]);
            afr1[kt][2] = pack_bf16x2(xc[c + 8], xc[c + 9]);
            afr1[kt][3] = pack_bf16x2(xd[c + 8], xd[c + 9]);
        }
    }

    const uint32_t s_base   = (uint32_t)__cvta_generic_to_shared(s_stage);
    const uint32_t lds_lane = (uint32_t)((lane & 7) * VQ_EPAD * 2 + (lane >> 3) * 16);
    __syncthreads();

    // ============ SINGLE SWEEP: mma + two-phase threshold capture ============
    float mn0 = 3.0e38f, mn1 = 3.0e38f, mn2 = 3.0e38f, mn3 = 3.0e38f;
    copy_chunk(0, s_base, tid);
    #pragma unroll 1
    for (int ch = 0; ch < VQ_NCHUNK; ch++) {
        if (ch + 1 < VQ_NCHUNK) { copy_chunk(ch + 1, s_base, tid); cp_wait1(); }
        else                    { cp_wait0(); }
        __syncthreads();
        // stale row mins from previous chunk boundary (valid for ch >= 1)
        float st0 = 3.0e38f, st1 = 3.0e38f, st2 = 3.0e38f, st3 = 3.0e38f;
        if (ch > 0) {
            st0 = s_rowmin[r0]; st1 = s_rowmin[r1];
            st2 = s_rowmin[r2]; st3 = s_rowmin[r3];
        }
        const uint32_t stage = s_base + (uint32_t)((ch & 1) * VQ_CHUNK_B);
        #pragma unroll 2
        for (int nt = 0; nt < VQ_CHUNK / 8; nt++) {
            uint32_t base = stage + (uint32_t)(nt * 8 * VQ_EPAD * 2) + lds_lane;
            uint32_t b0, b1, b2, b3, b4, b5, b6, b7;
            ldsm_x4(b0, b1, b2, b3, base);
            ldsm_x4(b4, b5, b6, b7, base + 64);
            float cA0 = 0.f, cA1 = 0.f, cA2 = 0.f, cA3 = 0.f;
            float cB0 = 0.f, cB1 = 0.f, cB2 = 0.f, cB3 = 0.f;
            float cC0 = 0.f, cC1 = 0.f, cC2 = 0.f, cC3 = 0.f;
            float cD0 = 0.f, cD1 = 0.f, cD2 = 0.f, cD3 = 0.f;
            mma_bf16(cA0, cA1, cA2, cA3, afr0[0][0], afr0[0][1], afr0[0][2], afr0[0][3], b0, b1);
            mma_bf16(cB0, cB1, cB2, cB3, afr0[2][0], afr0[2][1], afr0[2][2], afr0[2][3], b4, b5);
            mma_bf16(cC0, cC1, cC2, cC3, afr1[0][0], afr1[0][1], afr1[0][2], afr1[0][3], b0, b1);
            mma_bf16(cD0, cD1, cD2, cD3, afr1[2][0], afr1[2][1], afr1[2][2], afr1[2][3], b4, b5);
            mma_bf16(cA0, cA1, cA2, cA3, afr0[1][0], afr0[1][1], afr0[1][2], afr0[1][3], b2, b3);
            mma_bf16(cB0, cB1, cB2, cB3, afr0[3][0], afr0[3][1], afr0[3][2], afr0[3][3], b6, b7);
            mma_bf16(cC0, cC1, cC2, cC3, afr1[1][0], afr1[1][1], afr1[1][2], afr1[1][3], b2, b3);
            mma_bf16(cD0, cD1, cD2, cD3, afr1[3][0], afr1[3][1], afr1[3][2], afr1[3][3], b6, b7);
            float2 se = *reinterpret_cast<const float2*>(&s_Se[ch * VQ_CHUNK + nt * 8 + 2 * tg]);
            float d00 = fmaf(-2.f, cA0, fmaf(-2.f, cB0, se.x));
            float d01 = fmaf(-2.f, cA1, fmaf(-2.f, cB1, se.y));
            float d10 = fmaf(-2.f, cA2, fmaf(-2.f, cB2, se.x));
            float d11 = fmaf(-2.f, cA3, fmaf(-2.f, cB3, se.y));
            float d20 = fmaf(-2.f, cC0, fmaf(-2.f, cD0, se.x));
            float d21 = fmaf(-2.f, cC1, fmaf(-2.f, cD1, se.y));
            float d30 = fmaf(-2.f, cC2, fmaf(-2.f, cD2, se.x));
            float d31 = fmaf(-2.f, cC3, fmaf(-2.f, cD3, se.y));
            mn0 = fminf(mn0, fminf(d00, d01));
            mn1 = fminf(mn1, fminf(d10, d11));
            mn2 = fminf(mn2, fminf(d20, d21));
            mn3 = fminf(mn3, fminf(d30, d31));
            float thr0, thr1, thr2, thr3;
            if (ch == 0) {
                // per-tile row-level exchange (chunk 0 only: seeds lanes with row min)
                mn0 = fminf(mn0, __shfl_xor_sync(0xffffffffu, mn0, 1));
                mn0 = fminf(mn0, __shfl_xor_sync(0xffffffffu, mn0, 2));
                mn1 = fminf(mn1, __shfl_xor_sync(0xffffffffu, mn1, 1));
                mn1 = fminf(mn1, __shfl_xor_sync(0xffffffffu, mn1, 2));
                mn2 = fminf(mn2, __shfl_xor_sync(0xffffffffu, mn2, 1));
                mn2 = fminf(mn2, __shfl_xor_sync(0xffffffffu, mn2, 2));
                mn3 = fminf(mn3, __shfl_xor_sync(0xffffffffu, mn3, 1));
                mn3 = fminf(mn3, __shfl_xor_sync(0xffffffffu, mn3, 2));
                thr0 = mn0 + VQ_MARGIN;
                thr1 = mn1 + VQ_MARGIN;
                thr2 = mn2 + VQ_MARGIN;
                thr3 = mn3 + VQ_MARGIN;
            } else {
                thr0 = fminf(mn0, st0) + VQ_MARGIN;
                thr1 = fminf(mn1, st1) + VQ_MARGIN;
                thr2 = fminf(mn2, st2) + VQ_MARGIN;
                thr3 = fminf(mn3, st3) + VQ_MARGIN;
            }
            const int codeb = ch * VQ_CHUNK + nt * 8 + 2 * tg;
            if (d00 <= thr0) { int s = atomicAdd(&s_cnt[r0], 1); if (s < VQ_SLOTS) s_cand[r0][s] = codeb; }
            if (d01 <= thr0) { int s = atomicAdd(&s_cnt[r0], 1); if (s < VQ_SLOTS) s_cand[r0][s] = codeb + 1; }
            if (d10 <= thr1) { int s = atomicAdd(&s_cnt[r1], 1); if (s < VQ_SLOTS) s_cand[r1][s] = codeb; }
            if (d11 <= thr1) { int s = atomicAdd(&s_cnt[r1], 1); if (s < VQ_SLOTS) s_cand[r1][s] = codeb + 1; }
            if (d20 <= thr2) { int s = atomicAdd(&s_cnt[r2], 1); if (s < VQ_SLOTS) s_cand[r2][s] = codeb; }
            if (d21 <= thr2) { int s = atomicAdd(&s_cnt[r2], 1); if (s < VQ_SLOTS) s_cand[r2][s] = codeb + 1; }
            if (d30 <= thr3) { int s = atomicAdd(&s_cnt[r3], 1); if (s < VQ_SLOTS) s_cand[r3][s] = codeb; }
            if (d31 <= thr3) { int s = atomicAdd(&s_cnt[r3], 1); if (s < VQ_SLOTS) s_cand[r3][s] = codeb + 1; }
        }
        // refresh chunk-boundary row mins (lane tg==0 holds a full row view
        // only for ch==0; for ch>0 fold 4 lanes via smem-safe min writes)
        if (ch == 0) {
            if (tg == 0) {
                s_rowmin[r0] = mn0; s_rowmin[r1] = mn1;
                s_rowmin[r2] = mn2; s_rowmin[r3] = mn3;
            }
        } else {
            // 2-shfl exchange once per chunk (8 total across the sweep)
            float e0 = fminf(mn0, __shfl_xor_sync(0xffffffffu, mn0, 1));
            e0 = fminf(e0, __shfl_xor_sync(0xffffffffu, e0, 2));
            float e1 = fminf(mn1, __shfl_xor_sync(0xffffffffu, mn1, 1));
            e1 = fminf(e1, __shfl_xor_sync(0xffffffffu, e1, 2));
            float e2 = fminf(mn2, __shfl_xor_sync(0xffffffffu, mn2, 1));
            e2 = fminf(e2, __shfl_xor_sync(0xffffffffu, e2, 2));
            float e3 = fminf(mn3, __shfl_xor_sync(0xffffffffu, mn3, 1));
            e3 = fminf(e3, __shfl_xor_sync(0xffffffffu, e3, 2));
            if (tg == 0) {
                s_rowmin[r0] = e0; s_rowmin[r1] = e1;
                s_rowmin[r2] = e2; s_rowmin[r3] = e3;
            }
        }
        __syncthreads();
    }

    // ===== exact rescore: one thread per row, x streamed from L1 =====
    {
        const int row = rowbase + tid;
        const float4* xp = reinterpret_cast<const float4*>(x + (size_t)row * VQ_D);
        float Sx = 0.0f;
        #pragma unroll
        for (int i = 0; i < VQ_D / 4; i++) {
            float4 v = xp[i];
            Sx = fmaf(v.x, v.x, Sx); Sx = fmaf(v.y, v.y, Sx);
            Sx = fmaf(v.z, v.z, Sx); Sx = fmaf(v.w, v.w, Sx);
        }
        int   cnt  = s_cnt[tid];
        float best = 3.0e38f;
        int   bidx = VQ_K;
        if (cnt > VQ_SLOTS || cnt == 0) {
            for (int k = 0; k < VQ_K; k++) {     // rare overflow fallback
                float d = exact_dist_stream(xp, Sx, cb, s_Se, k);
                if (d < best) { best = d; bidx = k; }
            }
        } else {
            for (int s = 0; s < cnt; s++) {
                int k = s_cand[tid][s];
                float d = exact_dist_stream(xp, Sx, cb, s_Se, k);
                if (d < best || (d == best && k < bidx)) { best = d; bidx = k; }
            }
        }
        s_win[tid] = bidx;
    }
    __syncthreads();

    // ===== output + per-row loss (thread per row) =====
    float rl = 0.0f;
    {
        const int row = rowbase + tid;
        const int win = s_win[tid];
        const float4* xp = reinterpret_cast<const float4*>(x + (size_t)row * VQ_D);
        const float4* qp = reinterpret_cast<const float4*>(cb + (size_t)win * VQ_D);
        float4* op = reinterpret_cast<float4*>(out + (size_t)row * VQ_D);
        #pragma unroll
        for (int i = 0; i < VQ_D / 4; i++) {
            float4 q = qp[i], xv = xp[i];
            float rx = q.x - xv.x, ry = q.y - xv.y, rz = q.z - xv.z, rw = q.w - xv.w;
            if (write_q) {
                float4 o; o.x = xv.x + rx; o.y = xv.y + ry; o.z = xv.z + rz; o.w = xv.w + rw;
                op[i] = o;
            }
            rl = fmaf(rx, rx, rl); rl = fmaf(ry, ry, rl);
            rl = fmaf(rz, rz, rl); rl = fmaf(rw, rw, rl);
        }
    }
    s_red[tid] = rl;
    __syncthreads();
    #pragma unroll
    for (int s = VQ_TPB / 2; s > 0; s >>= 1) {
        if (tid < s) s_red[tid] += s_red[tid + s];
        __syncthreads();
    }

    // ===== fused loss: last-block ticket (deterministic, replay-safe) =====
    if (tid == 0) {
        g_vq_partial[blockIdx.x] = s_red[0];
        __threadfence();
        unsigned int t = atomicAdd(&g_vq_ticket, 1u);
        s_last = (t == VQ_GRID - 1) ? 1 : 0;
    }
    __syncthreads();
    if (s_last) {
        __threadfence();
        double acc = 0.0;
        for (int i = tid; i < VQ_GRID; i += VQ_TPB)
            acc += (double)g_vq_partial[i];
        s_dred[tid] = acc;
        __syncthreads();
        #pragma unroll
        for (int s = VQ_TPB / 2; s > 0; s >>= 1) {
            if (tid < s) s_dred[tid] += s_dred[tid + s];
            __syncthreads();
        }
        if (tid == 0) {
            double m = s_dred[0] / (double)((size_t)VQ_N * VQ_D);
            float loss = (float)(1.25 * m);
            const long long nq = (long long)VQ_N * VQ_D;
            if (out_size > nq) {
                for (long long i = nq; i < out_size; i++) out[i] = loss;
            } else if (out_size < nq && out_size > 0) {
                out[0] = loss;
            }
            g_vq_ticket = 0;
        }
    }
}

extern "C" void kernel_launch(void* const* d_in, const int* in_sizes, int n_in,
                              void* d_out, int out_size)
{
    const float* x  = (const float*)d_in[0];
    const float* cb = (const float*)d_in[1];
    float* out = (float*)d_out;

    const long long nq = (long long)VQ_N * VQ_D;
    int write_q = (out_size >= nq) ? 1 : 0;

    static int smem_configured = 0;
    if (!smem_configured) {
        cudaFuncSetAttribute(vq_main_kernel,
                             cudaFuncAttributeMaxDynamicSharedMemorySize, VQ_SMEM_E);
        smem_configured = 1;
    }

    vq_prep_kernel<<<VQ_K / VQ_TPB, VQ_TPB>>>(cb);
    vq_main_kernel<<<VQ_GRID, VQ_TPB, VQ_SMEM_E>>>(x, cb, out, write_q,
                                                   (long long)out_size);
}

// round 14
// speedup vs baseline: 2.2412x; 2.2412x over previous
#include <cuda_runtime.h>
#include <cuda_bf16.h>
#include <cstdint>

// VectorQuantizer: N=262144 rows, D=64, K=1024 codes, fp32.
//
// Round 14: R12 (342us, best) with ONE change: __launch_bounds__(256, 3)
// -> occupancy 3 (was 2, register-limited at 128 regs). R13's capture-in-sweep
// regressed 2x (tensor 36.9->8.7%): branchy per-tile capture serializes the
// mma stream. Lesson: sweep bodies must be branch-free; two clean sweeps win.
// Everything else identical to R12: two sweeps, 32 rows/warp, 4 indep mma
// chains, cp.async 2-stage codebook stream from bf16 prep buffer, candidate
// lists, exact rescore, fused ticket loss.
// Exact selection (validated, bit-identical): M = serial ascending-d fmaf
// chain, t = Sx + Se, d = fmaf(-2, M, t), argmin strict < ascending k.

#define VQ_N       262144
#define VQ_D       64
#define VQ_K       1024
#define VQ_TPB     256
#define VQ_ROWS_PB 256                    // 8 warps x 32 rows
#define VQ_GRID    (VQ_N / VQ_ROWS_PB)   // 1024 blocks
#define VQ_EPAD    72                    // padded bf16 row (144B)
#define VQ_CHUNK   128                   // codes per pipeline stage
#define VQ_NCHUNK  (VQ_K / VQ_CHUNK)     // 8
#define VQ_SLOTS   16
#define VQ_MARGIN  1e-3f

#define VQ_CHUNK_B (VQ_CHUNK * VQ_EPAD * 2)   // 18432 bytes per stage
#define VQ_SMEM_E  (2 * VQ_CHUNK_B)           // 36864 bytes dynamic

__device__ __nv_bfloat16 g_cbh[VQ_K * VQ_EPAD];   // bf16 codebook, padded rows
__device__ float         g_Se[VQ_K];              // exact serial-fmaf norms
__device__ float         g_vq_partial[VQ_GRID];
__device__ unsigned int  g_vq_ticket;             // zero-init; last block resets

__device__ __forceinline__ uint32_t pack_bf16x2(float lo, float hi) {
    __nv_bfloat162 h = __float22bfloat162_rn(make_float2(lo, hi));
    return *reinterpret_cast<uint32_t*>(&h);
}

__device__ __forceinline__ void mma_bf16(float& c0, float& c1, float& c2, float& c3,
                                         uint32_t a0, uint32_t a1, uint32_t a2, uint32_t a3,
                                         uint32_t b0, uint32_t b1) {
    asm volatile(
        "mma.sync.aligned.m16n8k16.row.col.f32.bf16.bf16.f32 "
        "{%0,%1,%2,%3},{%4,%5,%6,%7},{%8,%9},{%0,%1,%2,%3};"
        : "+f"(c0), "+f"(c1), "+f"(c2), "+f"(c3)
        : "r"(a0), "r"(a1), "r"(a2), "r"(a3), "r"(b0), "r"(b1));
}

__device__ __forceinline__ void ldsm_x4(uint32_t& r0, uint32_t& r1, uint32_t& r2, uint32_t& r3,
                                        uint32_t addr) {
    asm volatile("ldmatrix.sync.aligned.m8n8.x4.shared.b16 {%0,%1,%2,%3}, [%4];"
                 : "=r"(r0), "=r"(r1), "=r"(r2), "=r"(r3) : "r"(addr));
}

__device__ __forceinline__ void cp_async16(uint32_t dst_smem, const void* src) {
    asm volatile("cp.async.cg.shared.global [%0], [%1], 16;"
                 :: "r"(dst_smem), "l"(src));
}
__device__ __forceinline__ void cp_commit() { asm volatile("cp.async.commit_group;"); }
__device__ __forceinline__ void cp_wait1()  { asm volatile("cp.async.wait_group 1;"); }
__device__ __forceinline__ void cp_wait0()  { asm volatile("cp.async.wait_group 0;"); }

// Exact reference-rounding distance, streaming x from L1 (no register array).
__device__ __forceinline__ float exact_dist_stream(const float4* __restrict__ xp, float Sx,
                                                   const float* __restrict__ cb,
                                                   const float* __restrict__ se, int idx) {
    const float4* e4 = reinterpret_cast<const float4*>(cb + (size_t)idx * VQ_D);
    float m = 0.0f;
    #pragma unroll
    for (int i = 0; i < VQ_D / 4; i++) {
        float4 q = e4[i], xv = xp[i];
        m = fmaf(xv.x, q.x, m); m = fmaf(xv.y, q.y, m);
        m = fmaf(xv.z, q.z, m); m = fmaf(xv.w, q.w, m);
    }
    float t = Sx + se[idx];
    return fmaf(-2.0f, m, t);
}

// ---- prep: fp32 codebook -> bf16 padded global + exact Se ----
__global__ void vq_prep_kernel(const float* __restrict__ cb)
{
    int code = blockIdx.x * blockDim.x + threadIdx.x;
    if (code < VQ_K) {
        const float4* e4 = reinterpret_cast<const float4*>(cb + (size_t)code * VQ_D);
        uint32_t* dst = reinterpret_cast<uint32_t*>(g_cbh + code * VQ_EPAD);
        float s = 0.0f;
        #pragma unroll
        for (int i = 0; i < VQ_D / 4; i++) {
            float4 q = e4[i];
            s = fmaf(q.x, q.x, s); s = fmaf(q.y, q.y, s);
            s = fmaf(q.z, q.z, s); s = fmaf(q.w, q.w, s);
            dst[2 * i]     = pack_bf16x2(q.x, q.y);
            dst[2 * i + 1] = pack_bf16x2(q.z, q.w);
        }
        g_Se[code] = s;
    }
}

extern __shared__ __nv_bfloat16 s_stage[];   // 2 x VQ_CHUNK_B

__device__ __forceinline__ void copy_chunk(int ch, uint32_t s_base, int tid) {
    const char* src = reinterpret_cast<const char*>(g_cbh) + (size_t)ch * VQ_CHUNK_B;
    uint32_t dst = s_base + (uint32_t)((ch & 1) * VQ_CHUNK_B);
    #pragma unroll
    for (int i = tid; i < VQ_CHUNK_B / 16; i += VQ_TPB)
        cp_async16(dst + (uint32_t)(i * 16), src + i * 16);
    cp_commit();
}

__global__ void __launch_bounds__(VQ_TPB, 3)
vq_main_kernel(const float* __restrict__ x,
               const float* __restrict__ cb,
               float* __restrict__ out,
               int write_q, long long out_size)
{
    __shared__ float  s_Se[VQ_K];
    __shared__ float  s_rowmin[VQ_ROWS_PB];
    __shared__ int    s_cnt[VQ_ROWS_PB];
    __shared__ int    s_cand[VQ_ROWS_PB][VQ_SLOTS];
    __shared__ int    s_win[VQ_ROWS_PB];
    __shared__ float  s_red[VQ_TPB];
    __shared__ int    s_last;
    __shared__ double s_dred[VQ_TPB];

    const int tid  = threadIdx.x;
    const int wid  = tid >> 5;
    const int lane = tid & 31;
    const int g    = lane >> 2;
    const int tg   = lane & 3;
    const int rowbase = blockIdx.x * VQ_ROWS_PB;
    const int r0 = wid * 32 + g;
    const int r1 = r0 + 8;
    const int r2 = r0 + 16;
    const int r3 = r0 + 24;

    #pragma unroll
    for (int c = 0; c < VQ_K / VQ_TPB; c++)
        s_Se[tid + c * VQ_TPB] = g_Se[tid + c * VQ_TPB];
    s_cnt[tid] = 0;

    // ---- A fragments: warp's 32 rows as two m16 tiles, bf16 in regs ----
    uint32_t afr0[4][4], afr1[4][4];
    {
        const float* xa = x + (size_t)(rowbase + r0) * VQ_D;
        const float* xb = xa + 8 * VQ_D;
        const float* xc = xa + 16 * VQ_D;
        const float* xd = xa + 24 * VQ_D;
        #pragma unroll
        for (int kt = 0; kt < 4; kt++) {
            int c = kt * 16 + 2 * tg;
            afr0[kt][0] = pack_bf16x2(xa[c],     xa[c + 1]);
            afr0[kt][1] = pack_bf16x2(xb[c],     xb[c + 1]);
            afr0[kt][2] = pack_bf16x2(xa[c + 8], xa[c + 9]);
            afr0[kt][3] = pack_bf16x2(xb[c + 8], xb[c + 9]);
            afr1[kt][0] = pack_bf16x2(xc[c],     xc[c + 1]);
            afr1[kt][1] = pack_bf16x2(xd[c],     xd[c + 1]);
            afr1[kt][2] = pack_bf16x2(xc[c + 8], xc[c + 9]);
            afr1[kt][3] = pack_bf16x2(xd[c + 8], xd[c + 9]);
        }
    }

    const uint32_t s_base   = (uint32_t)__cvta_generic_to_shared(s_stage);
    const uint32_t lds_lane = (uint32_t)((lane & 7) * VQ_EPAD * 2 + (lane >> 3) * 16);
    __syncthreads();   // s_Se / s_cnt ready

    // =========================== SWEEP A ===========================
    float mn0 = 3.0e38f, mn1 = 3.0e38f, mn2 = 3.0e38f, mn3 = 3.0e38f;
    copy_chunk(0, s_base, tid);
    #pragma unroll 1
    for (int ch = 0; ch < VQ_NCHUNK; ch++) {
        if (ch + 1 < VQ_NCHUNK) { copy_chunk(ch + 1, s_base, tid); cp_wait1(); }
        else                    { cp_wait0(); }
        __syncthreads();
        const uint32_t stage = s_base + (uint32_t)((ch & 1) * VQ_CHUNK_B);
        #pragma unroll 2
        for (int nt = 0; nt < VQ_CHUNK / 8; nt++) {
            uint32_t base = stage + (uint32_t)(nt * 8 * VQ_EPAD * 2) + lds_lane;
            uint32_t b0, b1, b2, b3, b4, b5, b6, b7;
            ldsm_x4(b0, b1, b2, b3, base);
            ldsm_x4(b4, b5, b6, b7, base + 64);
            float cA0 = 0.f, cA1 = 0.f, cA2 = 0.f, cA3 = 0.f;
            float cB0 = 0.f, cB1 = 0.f, cB2 = 0.f, cB3 = 0.f;
            float cC0 = 0.f, cC1 = 0.f, cC2 = 0.f, cC3 = 0.f;
            float cD0 = 0.f, cD1 = 0.f, cD2 = 0.f, cD3 = 0.f;
            mma_bf16(cA0, cA1, cA2, cA3, afr0[0][0], afr0[0][1], afr0[0][2], afr0[0][3], b0, b1);
            mma_bf16(cB0, cB1, cB2, cB3, afr0[2][0], afr0[2][1], afr0[2][2], afr0[2][3], b4, b5);
            mma_bf16(cC0, cC1, cC2, cC3, afr1[0][0], afr1[0][1], afr1[0][2], afr1[0][3], b0, b1);
            mma_bf16(cD0, cD1, cD2, cD3, afr1[2][0], afr1[2][1], afr1[2][2], afr1[2][3], b4, b5);
            mma_bf16(cA0, cA1, cA2, cA3, afr0[1][0], afr0[1][1], afr0[1][2], afr0[1][3], b2, b3);
            mma_bf16(cB0, cB1, cB2, cB3, afr0[3][0], afr0[3][1], afr0[3][2], afr0[3][3], b6, b7);
            mma_bf16(cC0, cC1, cC2, cC3, afr1[1][0], afr1[1][1], afr1[1][2], afr1[1][3], b2, b3);
            mma_bf16(cD0, cD1, cD2, cD3, afr1[3][0], afr1[3][1], afr1[3][2], afr1[3][3], b6, b7);
            float2 se = *reinterpret_cast<const float2*>(&s_Se[ch * VQ_CHUNK + nt * 8 + 2 * tg]);
            float d00 = fmaf(-2.f, cA0, fmaf(-2.f, cB0, se.x));
            float d01 = fmaf(-2.f, cA1, fmaf(-2.f, cB1, se.y));
            float d10 = fmaf(-2.f, cA2, fmaf(-2.f, cB2, se.x));
            float d11 = fmaf(-2.f, cA3, fmaf(-2.f, cB3, se.y));
            float d20 = fmaf(-2.f, cC0, fmaf(-2.f, cD0, se.x));
            float d21 = fmaf(-2.f, cC1, fmaf(-2.f, cD1, se.y));
            float d30 = fmaf(-2.f, cC2, fmaf(-2.f, cD2, se.x));
            float d31 = fmaf(-2.f, cC3, fmaf(-2.f, cD3, se.y));
            mn0 = fminf(mn0, fminf(d00, d01));
            mn1 = fminf(mn1, fminf(d10, d11));
            mn2 = fminf(mn2, fminf(d20, d21));
            mn3 = fminf(mn3, fminf(d30, d31));
        }
        __syncthreads();
    }
    #pragma unroll
    for (int o = 1; o <= 2; o <<= 1) {
        mn0 = fminf(mn0, __shfl_xor_sync(0xffffffffu, mn0, o));
        mn1 = fminf(mn1, __shfl_xor_sync(0xffffffffu, mn1, o));
        mn2 = fminf(mn2, __shfl_xor_sync(0xffffffffu, mn2, o));
        mn3 = fminf(mn3, __shfl_xor_sync(0xffffffffu, mn3, o));
    }
    if (tg == 0) {
        s_rowmin[r0] = mn0;
        s_rowmin[r1] = mn1;
        s_rowmin[r2] = mn2;
        s_rowmin[r3] = mn3;
    }
    __syncthreads();

    const float thr0 = s_rowmin[r0] + VQ_MARGIN;
    const float thr1 = s_rowmin[r1] + VQ_MARGIN;
    const float thr2 = s_rowmin[r2] + VQ_MARGIN;
    const float thr3 = s_rowmin[r3] + VQ_MARGIN;

    // =========================== SWEEP B ===========================
    copy_chunk(0, s_base, tid);
    #pragma unroll 1
    for (int ch = 0; ch < VQ_NCHUNK; ch++) {
        if (ch + 1 < VQ_NCHUNK) { copy_chunk(ch + 1, s_base, tid); cp_wait1(); }
        else                    { cp_wait0(); }
        __syncthreads();
        const uint32_t stage = s_base + (uint32_t)((ch & 1) * VQ_CHUNK_B);
        #pragma unroll 2
        for (int nt = 0; nt < VQ_CHUNK / 8; nt++) {
            uint32_t base = stage + (uint32_t)(nt * 8 * VQ_EPAD * 2) + lds_lane;
            uint32_t b0, b1, b2, b3, b4, b5, b6, b7;
            ldsm_x4(b0, b1, b2, b3, base);
            ldsm_x4(b4, b5, b6, b7, base + 64);
            float cA0 = 0.f, cA1 = 0.f, cA2 = 0.f, cA3 = 0.f;
            float cB0 = 0.f, cB1 = 0.f, cB2 = 0.f, cB3 = 0.f;
            float cC0 = 0.f, cC1 = 0.f, cC2 = 0.f, cC3 = 0.f;
            float cD0 = 0.f, cD1 = 0.f, cD2 = 0.f, cD3 = 0.f;
            mma_bf16(cA0, cA1, cA2, cA3, afr0[0][0], afr0[0][1], afr0[0][2], afr0[0][3], b0, b1);
            mma_bf16(cB0, cB1, cB2, cB3, afr0[2][0], afr0[2][1], afr0[2][2], afr0[2][3], b4, b5);
            mma_bf16(cC0, cC1, cC2, cC3, afr1[0][0], afr1[0][1], afr1[0][2], afr1[0][3], b0, b1);
            mma_bf16(cD0, cD1, cD2, cD3, afr1[2][0], afr1[2][1], afr1[2][2], afr1[2][3], b4, b5);
            mma_bf16(cA0, cA1, cA2, cA3, afr0[1][0], afr0[1][1], afr0[1][2], afr0[1][3], b2, b3);
            mma_bf16(cB0, cB1, cB2, cB3, afr0[3][0], afr0[3][1], afr0[3][2], afr0[3][3], b6, b7);
            mma_bf16(cC0, cC1, cC2, cC3, afr1[1][0], afr1[1][1], afr1[1][2], afr1[1][3], b2, b3);
            mma_bf16(cD0, cD1, cD2, cD3, afr1[3][0], afr1[3][1], afr1[3][2], afr1[3][3], b6, b7);
            float2 se = *reinterpret_cast<const float2*>(&s_Se[ch * VQ_CHUNK + nt * 8 + 2 * tg]);
            float d00 = fmaf(-2.f, cA0, fmaf(-2.f, cB0, se.x));
            float d01 = fmaf(-2.f, cA1, fmaf(-2.f, cB1, se.y));
            float d10 = fmaf(-2.f, cA2, fmaf(-2.f, cB2, se.x));
            float d11 = fmaf(-2.f, cA3, fmaf(-2.f, cB3, se.y));
            float d20 = fmaf(-2.f, cC0, fmaf(-2.f, cD0, se.x));
            float d21 = fmaf(-2.f, cC1, fmaf(-2.f, cD1, se.y));
            float d30 = fmaf(-2.f, cC2, fmaf(-2.f, cD2, se.x));
            float d31 = fmaf(-2.f, cC3, fmaf(-2.f, cD3, se.y));
            const int codeb = ch * VQ_CHUNK + nt * 8 + 2 * tg;
            if (d00 <= thr0) { int s = atomicAdd(&s_cnt[r0], 1); if (s < VQ_SLOTS) s_cand[r0][s] = codeb; }
            if (d01 <= thr0) { int s = atomicAdd(&s_cnt[r0], 1); if (s < VQ_SLOTS) s_cand[r0][s] = codeb + 1; }
            if (d10 <= thr1) { int s = atomicAdd(&s_cnt[r1], 1); if (s < VQ_SLOTS) s_cand[r1][s] = codeb; }
            if (d11 <= thr1) { int s = atomicAdd(&s_cnt[r1], 1); if (s < VQ_SLOTS) s_cand[r1][s] = codeb + 1; }
            if (d20 <= thr2) { int s = atomicAdd(&s_cnt[r2], 1); if (s < VQ_SLOTS) s_cand[r2][s] = codeb; }
            if (d21 <= thr2) { int s = atomicAdd(&s_cnt[r2], 1); if (s < VQ_SLOTS) s_cand[r2][s] = codeb + 1; }
            if (d30 <= thr3) { int s = atomicAdd(&s_cnt[r3], 1); if (s < VQ_SLOTS) s_cand[r3][s] = codeb; }
            if (d31 <= thr3) { int s = atomicAdd(&s_cnt[r3], 1); if (s < VQ_SLOTS) s_cand[r3][s] = codeb + 1; }
        }
        __syncthreads();
    }
    __syncthreads();

    // ===== exact rescore: one thread per row, x streamed from L1 =====
    {
        const int row = rowbase + tid;
        const float4* xp = reinterpret_cast<const float4*>(x + (size_t)row * VQ_D);
        float Sx = 0.0f;
        #pragma unroll
        for (int i = 0; i < VQ_D / 4; i++) {
            float4 v = xp[i];
            Sx = fmaf(v.x, v.x, Sx); Sx = fmaf(v.y, v.y, Sx);
            Sx = fmaf(v.z, v.z, Sx); Sx = fmaf(v.w, v.w, Sx);
        }
        int   cnt  = s_cnt[tid];
        float best = 3.0e38f;
        int   bidx = VQ_K;
        if (cnt > VQ_SLOTS || cnt == 0) {
            for (int k = 0; k < VQ_K; k++) {     // statistically never
                float d = exact_dist_stream(xp, Sx, cb, s_Se, k);
                if (d < best) { best = d; bidx = k; }
            }
        } else {
            for (int s = 0; s < cnt; s++) {
                int k = s_cand[tid][s];
                float d = exact_dist_stream(xp, Sx, cb, s_Se, k);
                if (d < best || (d == best && k < bidx)) { best = d; bidx = k; }
            }
        }
        s_win[tid] = bidx;
    }
    __syncthreads();

    // ===== output + per-row loss (thread per row) =====
    float rl = 0.0f;
    {
        const int row = rowbase + tid;
        const int win = s_win[tid];
        const float4* xp = reinterpret_cast<const float4*>(x + (size_t)row * VQ_D);
        const float4* qp = reinterpret_cast<const float4*>(cb + (size_t)win * VQ_D);
        float4* op = reinterpret_cast<float4*>(out + (size_t)row * VQ_D);
        #pragma unroll
        for (int i = 0; i < VQ_D / 4; i++) {
            float4 q = qp[i], xv = xp[i];
            float rx = q.x - xv.x, ry = q.y - xv.y, rz = q.z - xv.z, rw = q.w - xv.w;
            if (write_q) {
                float4 o; o.x = xv.x + rx; o.y = xv.y + ry; o.z = xv.z + rz; o.w = xv.w + rw;
                op[i] = o;
            }
            rl = fmaf(rx, rx, rl); rl = fmaf(ry, ry, rl);
            rl = fmaf(rz, rz, rl); rl = fmaf(rw, rw, rl);
        }
    }
    s_red[tid] = rl;
    __syncthreads();
    #pragma unroll
    for (int s = VQ_TPB / 2; s > 0; s >>= 1) {
        if (tid < s) s_red[tid] += s_red[tid + s];
        __syncthreads();
    }

    // ===== fused loss: last-block ticket (deterministic, replay-safe) =====
    if (tid == 0) {
        g_vq_partial[blockIdx.x] = s_red[0];
        __threadfence();
        unsigned int t = atomicAdd(&g_vq_ticket, 1u);
        s_last = (t == VQ_GRID - 1) ? 1 : 0;
    }
    __syncthreads();
    if (s_last) {
        __threadfence();
        double acc = 0.0;
        for (int i = tid; i < VQ_GRID; i += VQ_TPB)
            acc += (double)g_vq_partial[i];
        s_dred[tid] = acc;
        __syncthreads();
        #pragma unroll
        for (int s = VQ_TPB / 2; s > 0; s >>= 1) {
            if (tid < s) s_dred[tid] += s_dred[tid + s];
            __syncthreads();
        }
        if (tid == 0) {
            double m = s_dred[0] / (double)((size_t)VQ_N * VQ_D);
            float loss = (float)(1.25 * m);
            const long long nq = (long long)VQ_N * VQ_D;
            if (out_size > nq) {
                for (long long i = nq; i < out_size; i++) out[i] = loss;
            } else if (out_size < nq && out_size > 0) {
                out[0] = loss;
            }
            g_vq_ticket = 0;
        }
    }
}

extern "C" void kernel_launch(void* const* d_in, const int* in_sizes, int n_in,
                              void* d_out, int out_size)
{
    const float* x  = (const float*)d_in[0];
    const float* cb = (const float*)d_in[1];
    float* out = (float*)d_out;

    const long long nq = (long long)VQ_N * VQ_D;
    int write_q = (out_size >= nq) ? 1 : 0;

    static int smem_configured = 0;
    if (!smem_configured) {
        cudaFuncSetAttribute(vq_main_kernel,
                             cudaFuncAttributeMaxDynamicSharedMemorySize, VQ_SMEM_E);
        smem_configured = 1;
    }

    vq_prep_kernel<<<VQ_K / VQ_TPB, VQ_TPB>>>(cb);
    vq_main_kernel<<<VQ_GRID, VQ_TPB, VQ_SMEM_E>>>(x, cb, out, write_q,
                                                   (long long)out_size);
}